// round 15
// baseline (speedup 1.0000x reference)
#include <cuda_runtime.h>
#include <cuda_fp16.h>
#include <cstdint>

// ---------------------------------------------------------------------------
// GatedSelfAttention  (B=16, LW=512, LE=128, L=640, D=1024, H=16, DH=64)
// R11: single fp16 end-to-end (all split lo-terms dropped).
// Error model: 6 iid fp16 rounding sources (~2.4e-4 each) => ~4.5e-4 total.
// ---------------------------------------------------------------------------

#define BB   16
#define LW   512
#define LE   128
#define LL   640
#define DD   1024
#define HH   16
#define DHH  64

typedef __half hf;

__device__ __forceinline__ uint32_t smem_u32(const void* p) {
    uint32_t a;
    asm("{ .reg .u64 t; cvta.to.shared.u64 t, %1; cvt.u32.u64 %0, t; }"
        : "=r"(a) : "l"(p));
    return a;
}

// ---------------- mma.sync / ldmatrix / cp.async helpers ----------------
#define LDX4(r, addr) \
    asm volatile("ldmatrix.sync.aligned.m8n8.x4.shared.b16 {%0,%1,%2,%3}, [%4];" \
        : "=r"((r)[0]), "=r"((r)[1]), "=r"((r)[2]), "=r"((r)[3]) : "r"(addr))

__device__ __forceinline__ void mma16816(float* c, const uint32_t* a,
                                         uint32_t b0, uint32_t b1) {
    asm volatile(
        "mma.sync.aligned.m16n8k16.row.col.f32.f16.f16.f32 "
        "{%0,%1,%2,%3}, {%4,%5,%6,%7}, {%8,%9}, {%0,%1,%2,%3};"
        : "+f"(c[0]), "+f"(c[1]), "+f"(c[2]), "+f"(c[3])
        : "r"(a[0]), "r"(a[1]), "r"(a[2]), "r"(a[3]), "r"(b0), "r"(b1));
}

__device__ __forceinline__ void cpa16(uint32_t s, const void* g) {
    asm volatile("cp.async.cg.shared.global [%0], [%1], 16;" :: "r"(s), "l"(g));
}
#define CP_COMMIT() asm volatile("cp.async.commit_group;" ::: "memory")
#define CP_WAIT(n)  asm volatile("cp.async.wait_group %0;" :: "n"(n) : "memory")

__device__ __forceinline__ unsigned short hfbits(hf h) {
    return *reinterpret_cast<unsigned short*>(&h);
}

// ---------------------------------------------------------------------------
// Scratch (device globals; allocation-free)
// ---------------------------------------------------------------------------
__device__ hf g_Qh  [BB*HH*LL*DHH];
__device__ hf g_Kh  [BB*HH*LL*DHH];
__device__ hf g_Vth [BB*HH*DHH*LL];       // transposed [bh][dh][L]
__device__ hf g_GQWh[BB*HH*LW*DHH];
__device__ hf g_GKWh[BB*HH*LW*DHH];
__device__ hf g_GQEh[BB*HH*LE*DHH];
__device__ hf g_GKEh[BB*HH*LE*DHH];

__device__ hf g_Xhi[BB*LL*DD];
__device__ hf g_Whi[7*DD*DD];             // weights transposed [N][K]

// ---------------------------------------------------------------------------
// Convert activations: word+entity fp32 -> concat [10240][1024] fp16
// ---------------------------------------------------------------------------
__global__ __launch_bounds__(256) void split_act(
    const float* __restrict__ word, const float* __restrict__ entity,
    hf* __restrict__ hi)
{
    int gid = blockIdx.x * 256 + threadIdx.x;
    int row = gid >> 8;
    int q   = gid & 255;
    int b = row / LL, l = row % LL;
    const float* src = (l < LW)
        ? word   + ((size_t)b * LW + l) * DD + q * 4
        : entity + ((size_t)b * LE + (l - LW)) * DD + q * 4;
    float4 x = *(const float4*)src;
    unsigned short hb[4];
    hb[0] = hfbits(__float2half_rn(x.x));
    hb[1] = hfbits(__float2half_rn(x.y));
    hb[2] = hfbits(__float2half_rn(x.z));
    hb[3] = hfbits(__float2half_rn(x.w));
    uint2 uh = { (uint32_t)hb[0] | ((uint32_t)hb[1] << 16),
                 (uint32_t)hb[2] | ((uint32_t)hb[3] << 16) };
    *(uint2*)(hi + (size_t)row * DD + q * 4) = uh;
}

// ---------------------------------------------------------------------------
// Transpose weights: W[K][N] fp32 -> Wt[N][K] fp16 (7 weights)
// ---------------------------------------------------------------------------
__global__ __launch_bounds__(256) void split_wt(
    const float* w0, const float* w1, const float* w2, const float* w3,
    const float* w4, const float* w5, const float* w6,
    hf* __restrict__ hi)
{
    __shared__ float tile[32][33];
    const float* ws[7] = {w0, w1, w2, w3, w4, w5, w6};
    const float* W = ws[blockIdx.z];
    hf* H = hi + (size_t)blockIdx.z * DD * DD;

    int k0 = blockIdx.y * 32, n0 = blockIdx.x * 32;
    int tx = threadIdx.x, ty = threadIdx.y;
#pragma unroll
    for (int j = 0; j < 4; j++)
        tile[ty + 8 * j][tx] = W[(size_t)(k0 + ty + 8 * j) * DD + n0 + tx];
    __syncthreads();
#pragma unroll
    for (int j = 0; j < 4; j++) {
        int r = ty + 8 * j;
        H[(size_t)(n0 + r) * DD + k0 + tx] = __float2half_rn(tile[tx][r]);
    }
}

// ---------------------------------------------------------------------------
// Merged HMMA projection GEMM (single fp16).
// One launch: 3200 CTAs, 7 segments. Per CTA: 128x128 tile, K=1024.
// SMEM per buffer: 2 parts x [128 rows x 80B] = 20 KB, double-buffered.
// ---------------------------------------------------------------------------
#define PPART 10240u
#define PBUF  20480u

__global__ __launch_bounds__(256, 2) void proj_all(
    const hf* __restrict__ Xhi, const hf* __restrict__ Wall,
    const float* b0, const float* b1, const float* b2, const float* b3,
    const float* b4, const float* b5, const float* b6,
    hf* o0, hf* o1, hf* o2, hf* o3, hf* o4, hf* o5, hf* o6)
{
    extern __shared__ char smc[];
    const uint32_t smb = smem_u32(smc);

    // ---- segment resolve ----
    int sid = 0, local = (int)blockIdx.x;
    {
        const int sz0 = 640, sz1 = 640, sz2 = 640, sz3 = 512,
                  sz4 = 128, sz5 = 128;
        if (local >= sz0) { local -= sz0; sid = 1;
        if (local >= sz1) { local -= sz1; sid = 2;
        if (local >= sz2) { local -= sz2; sid = 3;
        if (local >= sz3) { local -= sz3; sid = 4;
        if (local >= sz4) { local -= sz4; sid = 5;
        if (local >= sz5) { local -= sz5; sid = 6; } } } } } }
    }
    const float* bias; hf* outH; int Lx, rowOff, vtrans;
    switch (sid) {
    case 0: bias = b0; outH = o0; Lx = LL; rowOff = 0;  vtrans = 0; break;
    case 1: bias = b1; outH = o1; Lx = LL; rowOff = 0;  vtrans = 0; break;
    case 2: bias = b2; outH = o2; Lx = LL; rowOff = 0;  vtrans = 1; break;
    case 3: bias = b3; outH = o3; Lx = LW; rowOff = 0;  vtrans = 0; break;
    case 4: bias = b4; outH = o4; Lx = LE; rowOff = LW; vtrans = 0; break;
    case 5: bias = b5; outH = o5; Lx = LE; rowOff = LW; vtrans = 0; break;
    default:bias = b6; outH = o6; Lx = LW; rowOff = 0;  vtrans = 0; break;
    }
    const hf* Whi = Wall + (size_t)sid * DD * DD;

    const int tid  = threadIdx.x;
    const int wid  = tid >> 5;
    const int lane = tid & 31;
    const int wm = wid >> 2;
    const int wn = wid & 3;

    const int mBase = (local >> 3) * 128;
    const int nBase = (local & 7) * 128;
    const int b  = mBase / Lx;
    const int l0 = mBase % Lx;

    const hf* Ah = Xhi + ((size_t)b * LL + rowOff + l0) * DD;
    const hf* Bh = Whi + (size_t)nBase * DD;
    const hf* srcs[2] = {Ah, Bh};

    const int u0   = tid * 2;
    const int lrow = u0 >> 2;
    const int lcol = u0 & 3;

    const uint32_t a_off =
        (uint32_t)((wm * 64 + (lane & 15)) * 80 + (lane >> 4) * 16);
    const uint32_t b_off =
        (uint32_t)((wn * 32 + (lane & 7) + ((lane >> 4) & 1) * 8) * 80 +
                   ((lane >> 3) & 1) * 16);

    float acc[4][4][4];
#pragma unroll
    for (int mt = 0; mt < 4; mt++)
#pragma unroll
        for (int nt = 0; nt < 4; nt++)
#pragma unroll
            for (int i = 0; i < 4; i++) acc[mt][nt][i] = 0.0f;

    {
#pragma unroll
        for (int p = 0; p < 2; p++) {
            const hf* gp = srcs[p] + (size_t)lrow * DD + lcol * 8;
            uint32_t sp = smb + p * PPART + (uint32_t)(lrow * 80 + lcol * 16);
            cpa16(sp, gp);
            cpa16(sp + 16, gp + 8);
        }
        CP_COMMIT();
    }

    for (int c = 0; c < 32; c++) {
        const int buf = c & 1;
        if (c + 1 < 32) {
            const int k0 = (c + 1) * 32;
            const uint32_t bb = (uint32_t)(buf ^ 1) * PBUF;
#pragma unroll
            for (int p = 0; p < 2; p++) {
                const hf* gp = srcs[p] + (size_t)lrow * DD + k0 + lcol * 8;
                uint32_t sp = smb + bb + p * PPART + (uint32_t)(lrow * 80 + lcol * 16);
                cpa16(sp, gp);
                cpa16(sp + 16, gp + 8);
            }
            CP_COMMIT();
            CP_WAIT(1);
        } else {
            CP_WAIT(0);
        }
        __syncthreads();

        const uint32_t base = smb + (uint32_t)buf * PBUF;
#pragma unroll
        for (int k16 = 0; k16 < 2; k16++) {
            const uint32_t kb = (uint32_t)k16 * 32;
            uint32_t ah[4][4], bh[2][4];
#pragma unroll
            for (int mt = 0; mt < 4; mt++)
                LDX4(ah[mt], base + 0 * PPART + a_off + (uint32_t)(mt * 16 * 80) + kb);
#pragma unroll
            for (int np = 0; np < 2; np++)
                LDX4(bh[np], base + 1 * PPART + b_off + (uint32_t)(np * 16 * 80) + kb);
#pragma unroll
            for (int mt = 0; mt < 4; mt++)
#pragma unroll
                for (int nt = 0; nt < 4; nt++)
                    mma16816(acc[mt][nt], ah[mt], bh[nt >> 1][(nt & 1) * 2],
                             bh[nt >> 1][(nt & 1) * 2 + 1]);
        }
        __syncthreads();
    }

    // epilogue: bias add, fp16 round, store
#pragma unroll
    for (int mt = 0; mt < 4; mt++) {
        const int lloc = l0 + wm * 64 + mt * 16 + (lane >> 2);
#pragma unroll
        for (int nt = 0; nt < 4; nt++) {
            const int n  = nBase + wn * 32 + nt * 8 + (lane & 3) * 2;
            const int h  = n >> 6;
            const int dh = n & 63;
            const float bx = bias[n], by = bias[n + 1];
            unsigned short h00 = hfbits(__float2half_rn(acc[mt][nt][0] + bx));
            unsigned short h01 = hfbits(__float2half_rn(acc[mt][nt][1] + by));
            unsigned short h10 = hfbits(__float2half_rn(acc[mt][nt][2] + bx));
            unsigned short h11 = hfbits(__float2half_rn(acc[mt][nt][3] + by));
            if (!vtrans) {
                size_t e0 = (((size_t)b * HH + h) * Lx + lloc) * DHH + dh;
                size_t e1 = e0 + 8 * DHH;
                *(uint32_t*)(outH + e0) = (uint32_t)h00 | ((uint32_t)h01 << 16);
                *(uint32_t*)(outH + e1) = (uint32_t)h10 | ((uint32_t)h11 << 16);
            } else {
                size_t t0 = (((size_t)b * HH + h) * DHH + dh) * Lx + lloc;
                outH[t0]          = *reinterpret_cast<hf*>(&h00);
                outH[t0 + 8]      = *reinterpret_cast<hf*>(&h10);
                outH[t0 + Lx]     = *reinterpret_cast<hf*>(&h01);
                outH[t0 + Lx + 8] = *reinterpret_cast<hf*>(&h11);
            }
        }
    }
}

// ---------------------------------------------------------------------------
// HMMA fused attention (single fp16).  CTA = 128 q rows, 10 kv tiles of 64.
// Regions: QH 0 (16K) | R1 16384 (Gq -> P, 16K) | R2 32768 (Gk/K, 8K) |
//          VH 40960 (8K) | MS 49152 (256B)   total 49408 B
// ---------------------------------------------------------------------------
#define SM_QH  0u
#define SM_R1  16384u
#define SM_R2  32768u
#define SM_VH  40960u
#define SM_MS  49152u
#define ATT_SMEM 49408u

__device__ __forceinline__ uint32_t swz(uint32_t base, int row, int c16) {
    return base + (uint32_t)(row * 128) + (uint32_t)(((c16 ^ (row & 7)) << 4));
}

// single-term GEMM tile: acc[8][4] += A(16 rows/warp x 64) * B(64 x 64)
__device__ __forceinline__ void gemm1(
    float (*acc)[4], uint32_t Ab, uint32_t Bb,
    int aRow, int bRow0, int aC, int bC)
{
#pragma unroll
    for (int s = 0; s < 4; s++) {
        uint32_t ah[4];
        LDX4(ah, swz(Ab, aRow, 2 * s + aC));
#pragma unroll
        for (int ntp = 0; ntp < 4; ntp++) {
            int br = bRow0 + ntp * 16;
            uint32_t bhf[4];
            LDX4(bhf, swz(Bb, br, 2 * s + bC));
            mma16816(acc[2*ntp],   ah, bhf[0], bhf[1]);
            mma16816(acc[2*ntp+1], ah, bhf[2], bhf[3]);
        }
    }
}

__global__ __launch_bounds__(256, 2) void attn_mma(
    const hf* __restrict__ Qh,  const hf* __restrict__ Kh,
    const hf* __restrict__ Vth,
    const hf* __restrict__ GQWh,const hf* __restrict__ GQEh,
    const hf* __restrict__ GKWh,const hf* __restrict__ GKEh,
    const float* __restrict__ mask, float* __restrict__ out)
{
    extern __shared__ char smc[];
    const uint32_t smb = smem_u32(smc);

    const int tid  = threadIdx.x;
    const int wid  = tid >> 5;
    const int lane = tid & 31;

    const int qt = blockIdx.x;          // 0..4
    const int h  = blockIdx.y;
    const int b  = blockIdx.z;
    const int q0 = qt * 128;
    const bool qWord = (q0 < LW);
    const size_t bh = (size_t)(b * HH + h);

    const hf* Qhg = Qh + (bh * LL + q0) * DHH;
    const hf* Gqh = qWord ? GQWh + (bh * LW + q0) * DHH
                          : GQEh + (bh * LE + (q0 - LW)) * DHH;

    // stage Q (once): 128 rows x 8 units of 16B
#pragma unroll
    for (int u = tid; u < 1024; u += 256) {
        int row = u >> 3, c = u & 7;
        cpa16(swz(smb + SM_QH, row, c), Qhg + (size_t)row * DHH + c * 8);
    }
    CP_COMMIT();

    const int aRow  = wid * 16 + (lane & 15);
    const int aC    = lane >> 4;
    const int bRow0 = (lane & 7) + ((lane >> 4) & 1) * 8;
    const int bC    = (lane >> 3) & 1;

    float o[8][4];
#pragma unroll
    for (int t = 0; t < 8; t++)
#pragma unroll
        for (int j = 0; j < 4; j++) o[t][j] = 0.0f;
    float m0 = -1e30f, m1 = -1e30f, ls0 = 0.0f, ls1 = 0.0f;

    const int r0  = wid * 16 + (lane >> 2);
    const int prx = r0 & 7;
    const int pb  = 4 * (lane & 3);

    for (int kt = 0; kt < 10; kt++) {
        const int  k0    = kt * 64;
        const bool kWord = (k0 < LW);
        const bool cross = (kWord != qWord);

        __syncthreads();

        // ---- stage this iteration ----
        {
            if (cross) {
                const hf* gkh = qWord ? GKEh + (bh * LE + (k0 - LW)) * DHH
                                      : GKWh + (bh * LW + k0) * DHH;
#pragma unroll
                for (int u = tid; u < 1024; u += 256) {
                    int rr = u >> 3, cc = u & 7;
                    cpa16(swz(smb + SM_R1, rr, cc), Gqh + (size_t)rr * DHH + cc * 8);
                }
#pragma unroll
                for (int u = tid; u < 512; u += 256) {
                    int rr = u >> 3, cc = u & 7;
                    cpa16(swz(smb + SM_R2, rr, cc), gkh + (size_t)rr * DHH + cc * 8);
                }
            } else {
                const hf* kh = Kh + (bh * LL + k0) * DHH;
#pragma unroll
                for (int u = tid; u < 512; u += 256) {
                    int rr = u >> 3, cc = u & 7;
                    cpa16(swz(smb + SM_R2, rr, cc), kh + (size_t)rr * DHH + cc * 8);
                }
            }
            const hf* vhB = Vth + bh * DHH * LL + k0;
#pragma unroll
            for (int u = tid; u < 512; u += 256) {
                int rr = u >> 3, cc = u & 7;
                cpa16(swz(smb + SM_VH, rr, cc), vhB + (size_t)rr * LL + cc * 8);
            }
            if (tid < 16)
                cpa16(smb + SM_MS + tid * 16, mask + (size_t)b * LL + k0 + tid * 4);
            CP_COMMIT();
            CP_WAIT(0);
            __syncthreads();
        }

        float acc[8][4];
        if (cross) {
            // gate GEMM -> sigmoid transform -> becomes accumulator init
#pragma unroll
            for (int t = 0; t < 8; t++)
#pragma unroll
                for (int j = 0; j < 4; j++) acc[t][j] = 0.0f;
            gemm1(acc, smb + SM_R1, smb + SM_R2, aRow, bRow0, aC, bC);
#pragma unroll
            for (int t = 0; t < 8; t++)
#pragma unroll
                for (int j = 0; j < 4; j++)
                    acc[t][j] = -10.0f / (1.0f + __expf(-acc[t][j]));
            __syncthreads();   // done reading Gk from R2
            {
                const hf* kh = Kh + (bh * LL + k0) * DHH;
#pragma unroll
                for (int u = tid; u < 512; u += 256) {
                    int rr = u >> 3, cc = u & 7;
                    cpa16(swz(smb + SM_R2, rr, cc), kh + (size_t)rr * DHH + cc * 8);
                }
                CP_COMMIT();
                CP_WAIT(0);
                __syncthreads();
            }
        } else {
#pragma unroll
            for (int t = 0; t < 8; t++)
#pragma unroll
                for (int j = 0; j < 4; j++) acc[t][j] = -5.0f;
        }

        // S GEMM: Q * K^T accumulated onto gate
        gemm1(acc, smb + SM_QH, smb + SM_R2, aRow, bRow0, aC, bC);

        // ---- online softmax ----
        float rmax0 = -1e30f, rmax1 = -1e30f;
#pragma unroll
        for (int t = 0; t < 8; t++) {
            int colb = t * 8 + 2 * (lane & 3);
            float mk0 = *(const float*)(smc + SM_MS + (colb) * 4);
            float mk1 = *(const float*)(smc + SM_MS + (colb + 1) * 4);
            acc[t][0] = acc[t][0] * 0.125f + mk0;
            acc[t][1] = acc[t][1] * 0.125f + mk1;
            acc[t][2] = acc[t][2] * 0.125f + mk0;
            acc[t][3] = acc[t][3] * 0.125f + mk1;
            rmax0 = fmaxf(rmax0, fmaxf(acc[t][0], acc[t][1]));
            rmax1 = fmaxf(rmax1, fmaxf(acc[t][2], acc[t][3]));
        }
#pragma unroll
        for (int off = 1; off <= 2; off <<= 1) {
            rmax0 = fmaxf(rmax0, __shfl_xor_sync(0xffffffffu, rmax0, off));
            rmax1 = fmaxf(rmax1, __shfl_xor_sync(0xffffffffu, rmax1, off));
        }
        float mn0 = fmaxf(m0, rmax0), mn1 = fmaxf(m1, rmax1);
        float corr0 = __expf(m0 - mn0), corr1 = __expf(m1 - mn1);
        m0 = mn0; m1 = mn1;
        float sum0 = 0.0f, sum1 = 0.0f;
#pragma unroll
        for (int t = 0; t < 8; t++) {
            acc[t][0] = __expf(acc[t][0] - mn0);
            acc[t][1] = __expf(acc[t][1] - mn0);
            acc[t][2] = __expf(acc[t][2] - mn1);
            acc[t][3] = __expf(acc[t][3] - mn1);
            sum0 += acc[t][0] + acc[t][1];
            sum1 += acc[t][2] + acc[t][3];
        }
#pragma unroll
        for (int off = 1; off <= 2; off <<= 1) {
            sum0 += __shfl_xor_sync(0xffffffffu, sum0, off);
            sum1 += __shfl_xor_sync(0xffffffffu, sum1, off);
        }
        ls0 = ls0 * corr0 + sum0;
        ls1 = ls1 * corr1 + sum1;
#pragma unroll
        for (int t = 0; t < 8; t++) {
            o[t][0] *= corr0; o[t][1] *= corr0;
            o[t][2] *= corr1; o[t][3] *= corr1;
        }

        // ---- store P (fp16) into R1 ----
#pragma unroll
        for (int t = 0; t < 8; t++) {
            unsigned short h00 = hfbits(__float2half_rn(acc[t][0]));
            unsigned short h01 = hfbits(__float2half_rn(acc[t][1]));
            unsigned short h10 = hfbits(__float2half_rn(acc[t][2]));
            unsigned short h11 = hfbits(__float2half_rn(acc[t][3]));
            uint32_t ofs = (uint32_t)(r0 * 128 + ((t ^ prx) << 4) + pb);
            *(uint32_t*)(smc + SM_R1 + ofs) = (uint32_t)h00 | ((uint32_t)h01 << 16);
            *(uint32_t*)(smc + SM_R1 + ofs + 1024) = (uint32_t)h10 | ((uint32_t)h11 << 16);
        }
        __syncthreads();

        // ---- PV GEMM: P * V^T ----
        gemm1(o, smb + SM_R1, smb + SM_VH, aRow, bRow0, aC, bC);
    }

    // ---- epilogue ----
    float inv0 = 1.0f / ls0, inv1 = 1.0f / ls1;
    int q  = q0 + r0;
    size_t off0, off1;
    if (q < LW) {
        off0 = ((size_t)b * LW + q) * DD + h * DHH;
        off1 = ((size_t)b * LW + q + 8) * DD + h * DHH;
    } else {
        off0 = (size_t)BB * LW * DD + ((size_t)b * LE + (q - LW)) * DD + h * DHH;
        off1 = off0 + 8 * DD;
    }
#pragma unroll
    for (int t = 0; t < 8; t++) {
        int dh = t * 8 + 2 * (lane & 3);
        float2 r0v = {o[t][0] * inv0, o[t][1] * inv0};
        float2 r1v = {o[t][2] * inv1, o[t][3] * inv1};
        *(float2*)(out + off0 + dh) = r0v;
        *(float2*)(out + off1 + dh) = r1v;
    }
}

// ---------------------------------------------------------------------------
// Launch
// ---------------------------------------------------------------------------
extern "C" void kernel_launch(void* const* d_in, const int* in_sizes, int n_in,
                              void* d_out, int out_size)
{
    const float* word   = (const float*)d_in[0];
    const float* entity = (const float*)d_in[1];
    const float* mask   = (const float*)d_in[2];
    int base = (in_sizes[3] == 1) ? 4 : 3;
    const float* qw     = (const float*)d_in[base + 0];
    const float* qb     = (const float*)d_in[base + 1];
    const float* kw     = (const float*)d_in[base + 2];
    const float* kb     = (const float*)d_in[base + 3];
    const float* vw     = (const float*)d_in[base + 4];
    const float* vb     = (const float*)d_in[base + 5];
    const float* w2e_qw = (const float*)d_in[base + 6];
    const float* w2e_qb = (const float*)d_in[base + 7];
    const float* w2e_kw = (const float*)d_in[base + 8];
    const float* w2e_kb = (const float*)d_in[base + 9];
    const float* e2w_qw = (const float*)d_in[base + 10];
    const float* e2w_qb = (const float*)d_in[base + 11];
    const float* e2w_kw = (const float*)d_in[base + 12];
    const float* e2w_kb = (const float*)d_in[base + 13];

    hf *pQh,*pKh,*pVth,*pGQWh,*pGKWh,*pGQEh,*pGKEh,*pXhi,*pWhi;
    cudaGetSymbolAddress((void**)&pQh,  g_Qh);
    cudaGetSymbolAddress((void**)&pKh,  g_Kh);
    cudaGetSymbolAddress((void**)&pVth, g_Vth);
    cudaGetSymbolAddress((void**)&pGQWh,g_GQWh);
    cudaGetSymbolAddress((void**)&pGKWh,g_GKWh);
    cudaGetSymbolAddress((void**)&pGQEh,g_GQEh);
    cudaGetSymbolAddress((void**)&pGKEh,g_GKEh);
    cudaGetSymbolAddress((void**)&pXhi, g_Xhi);
    cudaGetSymbolAddress((void**)&pWhi, g_Whi);

    // ---- convert pass ----
    split_act<<<BB * LL, 256>>>(word, entity, pXhi);
    split_wt<<<dim3(32, 32, 7), dim3(32, 8)>>>(
        qw, kw, vw, w2e_qw, w2e_kw, e2w_qw, e2w_kw, pWhi);

    // ---- merged HMMA projections (one launch, 3200 CTAs) ----
    const size_t psmem = 2 * PBUF;   // 40 KB
    cudaFuncSetAttribute(proj_all,
                         cudaFuncAttributeMaxDynamicSharedMemorySize, (int)psmem);
    proj_all<<<3200, 256, psmem>>>(
        pXhi, pWhi,
        qb, kb, vb, w2e_qb, w2e_kb, e2w_qb, e2w_kb,
        pQh, pKh, pVth, pGQWh, pGKEh, pGQEh, pGKWh);

    // ---- HMMA attention ----
    cudaFuncSetAttribute(attn_mma,
                         cudaFuncAttributeMaxDynamicSharedMemorySize, (int)ATT_SMEM);
    attn_mma<<<dim3(5, HH, BB), 256, ATT_SMEM>>>(
        pQh, pKh, pVth,
        pGQWh, pGQEh, pGKWh, pGKEh,
        mask, (float*)d_out);
}

// round 16
// speedup vs baseline: 1.0022x; 1.0022x over previous
#include <cuda_runtime.h>
#include <cuda_fp16.h>
#include <cstdint>

// ---------------------------------------------------------------------------
// GatedSelfAttention  (B=16, LW=512, LE=128, L=640, D=1024, H=16, DH=64)
// R11: single fp16 end-to-end (all split lo-terms dropped).
// Error model: 6 iid fp16 rounding sources (~2.4e-4 each) => ~4.5e-4 total.
// ---------------------------------------------------------------------------

#define BB   16
#define LW   512
#define LE   128
#define LL   640
#define DD   1024
#define HH   16
#define DHH  64

typedef __half hf;

__device__ __forceinline__ uint32_t smem_u32(const void* p) {
    uint32_t a;
    asm("{ .reg .u64 t; cvta.to.shared.u64 t, %1; cvt.u32.u64 %0, t; }"
        : "=r"(a) : "l"(p));
    return a;
}

// ---------------- mma.sync / ldmatrix / cp.async helpers ----------------
#define LDX4(r, addr) \
    asm volatile("ldmatrix.sync.aligned.m8n8.x4.shared.b16 {%0,%1,%2,%3}, [%4];" \
        : "=r"((r)[0]), "=r"((r)[1]), "=r"((r)[2]), "=r"((r)[3]) : "r"(addr))

__device__ __forceinline__ void mma16816(float* c, const uint32_t* a,
                                         uint32_t b0, uint32_t b1) {
    asm volatile(
        "mma.sync.aligned.m16n8k16.row.col.f32.f16.f16.f32 "
        "{%0,%1,%2,%3}, {%4,%5,%6,%7}, {%8,%9}, {%0,%1,%2,%3};"
        : "+f"(c[0]), "+f"(c[1]), "+f"(c[2]), "+f"(c[3])
        : "r"(a[0]), "r"(a[1]), "r"(a[2]), "r"(a[3]), "r"(b0), "r"(b1));
}

__device__ __forceinline__ void cpa16(uint32_t s, const void* g) {
    asm volatile("cp.async.cg.shared.global [%0], [%1], 16;" :: "r"(s), "l"(g));
}
#define CP_COMMIT() asm volatile("cp.async.commit_group;" ::: "memory")
#define CP_WAIT(n)  asm volatile("cp.async.wait_group %0;" :: "n"(n) : "memory")

__device__ __forceinline__ unsigned short hfbits(hf h) {
    return *reinterpret_cast<unsigned short*>(&h);
}

// ---------------------------------------------------------------------------
// Scratch (device globals; allocation-free)
// ---------------------------------------------------------------------------
__device__ hf g_Qh  [BB*HH*LL*DHH];
__device__ hf g_Kh  [BB*HH*LL*DHH];
__device__ hf g_Vth [BB*HH*DHH*LL];       // transposed [bh][dh][L]
__device__ hf g_GQWh[BB*HH*LW*DHH];
__device__ hf g_GKWh[BB*HH*LW*DHH];
__device__ hf g_GQEh[BB*HH*LE*DHH];
__device__ hf g_GKEh[BB*HH*LE*DHH];

__device__ hf g_Xhi[BB*LL*DD];
__device__ hf g_Whi[7*DD*DD];             // weights transposed [N][K]

// ---------------------------------------------------------------------------
// Convert activations: word+entity fp32 -> concat [10240][1024] fp16
// ---------------------------------------------------------------------------
__global__ __launch_bounds__(256) void split_act(
    const float* __restrict__ word, const float* __restrict__ entity,
    hf* __restrict__ hi)
{
    int gid = blockIdx.x * 256 + threadIdx.x;
    int row = gid >> 8;
    int q   = gid & 255;
    int b = row / LL, l = row % LL;
    const float* src = (l < LW)
        ? word   + ((size_t)b * LW + l) * DD + q * 4
        : entity + ((size_t)b * LE + (l - LW)) * DD + q * 4;
    float4 x = *(const float4*)src;
    unsigned short hb[4];
    hb[0] = hfbits(__float2half_rn(x.x));
    hb[1] = hfbits(__float2half_rn(x.y));
    hb[2] = hfbits(__float2half_rn(x.z));
    hb[3] = hfbits(__float2half_rn(x.w));
    uint2 uh = { (uint32_t)hb[0] | ((uint32_t)hb[1] << 16),
                 (uint32_t)hb[2] | ((uint32_t)hb[3] << 16) };
    *(uint2*)(hi + (size_t)row * DD + q * 4) = uh;
}

// ---------------------------------------------------------------------------
// Transpose weights: W[K][N] fp32 -> Wt[N][K] fp16 (7 weights)
// ---------------------------------------------------------------------------
__global__ __launch_bounds__(256) void split_wt(
    const float* w0, const float* w1, const float* w2, const float* w3,
    const float* w4, const float* w5, const float* w6,
    hf* __restrict__ hi)
{
    __shared__ float tile[32][33];
    const float* ws[7] = {w0, w1, w2, w3, w4, w5, w6};
    const float* W = ws[blockIdx.z];
    hf* H = hi + (size_t)blockIdx.z * DD * DD;

    int k0 = blockIdx.y * 32, n0 = blockIdx.x * 32;
    int tx = threadIdx.x, ty = threadIdx.y;
#pragma unroll
    for (int j = 0; j < 4; j++)
        tile[ty + 8 * j][tx] = W[(size_t)(k0 + ty + 8 * j) * DD + n0 + tx];
    __syncthreads();
#pragma unroll
    for (int j = 0; j < 4; j++) {
        int r = ty + 8 * j;
        H[(size_t)(n0 + r) * DD + k0 + tx] = __float2half_rn(tile[tx][r]);
    }
}

// ---------------------------------------------------------------------------
// Merged HMMA projection GEMM (single fp16).
// One launch: 3200 CTAs, 7 segments. Per CTA: 128x128 tile, K=1024.
// SMEM per buffer: 2 parts x [128 rows x 80B] = 20 KB, double-buffered.
// ---------------------------------------------------------------------------
#define PPART 10240u
#define PBUF  20480u

__global__ __launch_bounds__(256, 2) void proj_all(
    const hf* __restrict__ Xhi, const hf* __restrict__ Wall,
    const float* b0, const float* b1, const float* b2, const float* b3,
    const float* b4, const float* b5, const float* b6,
    hf* o0, hf* o1, hf* o2, hf* o3, hf* o4, hf* o5, hf* o6)
{
    extern __shared__ char smc[];
    const uint32_t smb = smem_u32(smc);

    // ---- segment resolve ----
    int sid = 0, local = (int)blockIdx.x;
    {
        const int sz0 = 640, sz1 = 640, sz2 = 640, sz3 = 512,
                  sz4 = 128, sz5 = 128;
        if (local >= sz0) { local -= sz0; sid = 1;
        if (local >= sz1) { local -= sz1; sid = 2;
        if (local >= sz2) { local -= sz2; sid = 3;
        if (local >= sz3) { local -= sz3; sid = 4;
        if (local >= sz4) { local -= sz4; sid = 5;
        if (local >= sz5) { local -= sz5; sid = 6; } } } } } }
    }
    const float* bias; hf* outH; int Lx, rowOff, vtrans;
    switch (sid) {
    case 0: bias = b0; outH = o0; Lx = LL; rowOff = 0;  vtrans = 0; break;
    case 1: bias = b1; outH = o1; Lx = LL; rowOff = 0;  vtrans = 0; break;
    case 2: bias = b2; outH = o2; Lx = LL; rowOff = 0;  vtrans = 1; break;
    case 3: bias = b3; outH = o3; Lx = LW; rowOff = 0;  vtrans = 0; break;
    case 4: bias = b4; outH = o4; Lx = LE; rowOff = LW; vtrans = 0; break;
    case 5: bias = b5; outH = o5; Lx = LE; rowOff = LW; vtrans = 0; break;
    default:bias = b6; outH = o6; Lx = LW; rowOff = 0;  vtrans = 0; break;
    }
    const hf* Whi = Wall + (size_t)sid * DD * DD;

    const int tid  = threadIdx.x;
    const int wid  = tid >> 5;
    const int lane = tid & 31;
    const int wm = wid >> 2;
    const int wn = wid & 3;

    const int mBase = (local >> 3) * 128;
    const int nBase = (local & 7) * 128;
    const int b  = mBase / Lx;
    const int l0 = mBase % Lx;

    const hf* Ah = Xhi + ((size_t)b * LL + rowOff + l0) * DD;
    const hf* Bh = Whi + (size_t)nBase * DD;
    const hf* srcs[2] = {Ah, Bh};

    const int u0   = tid * 2;
    const int lrow = u0 >> 2;
    const int lcol = u0 & 3;

    const uint32_t a_off =
        (uint32_t)((wm * 64 + (lane & 15)) * 80 + (lane >> 4) * 16);
    const uint32_t b_off =
        (uint32_t)((wn * 32 + (lane & 7) + ((lane >> 4) & 1) * 8) * 80 +
                   ((lane >> 3) & 1) * 16);

    float acc[4][4][4];
#pragma unroll
    for (int mt = 0; mt < 4; mt++)
#pragma unroll
        for (int nt = 0; nt < 4; nt++)
#pragma unroll
            for (int i = 0; i < 4; i++) acc[mt][nt][i] = 0.0f;

    {
#pragma unroll
        for (int p = 0; p < 2; p++) {
            const hf* gp = srcs[p] + (size_t)lrow * DD + lcol * 8;
            uint32_t sp = smb + p * PPART + (uint32_t)(lrow * 80 + lcol * 16);
            cpa16(sp, gp);
            cpa16(sp + 16, gp + 8);
        }
        CP_COMMIT();
    }

    for (int c = 0; c < 32; c++) {
        const int buf = c & 1;
        if (c + 1 < 32) {
            const int k0 = (c + 1) * 32;
            const uint32_t bb = (uint32_t)(buf ^ 1) * PBUF;
#pragma unroll
            for (int p = 0; p < 2; p++) {
                const hf* gp = srcs[p] + (size_t)lrow * DD + k0 + lcol * 8;
                uint32_t sp = smb + bb + p * PPART + (uint32_t)(lrow * 80 + lcol * 16);
                cpa16(sp, gp);
                cpa16(sp + 16, gp + 8);
            }
            CP_COMMIT();
            CP_WAIT(1);
        } else {
            CP_WAIT(0);
        }
        __syncthreads();

        const uint32_t base = smb + (uint32_t)buf * PBUF;
#pragma unroll
        for (int k16 = 0; k16 < 2; k16++) {
            const uint32_t kb = (uint32_t)k16 * 32;
            uint32_t ah[4][4], bh[2][4];
#pragma unroll
            for (int mt = 0; mt < 4; mt++)
                LDX4(ah[mt], base + 0 * PPART + a_off + (uint32_t)(mt * 16 * 80) + kb);
#pragma unroll
            for (int np = 0; np < 2; np++)
                LDX4(bh[np], base + 1 * PPART + b_off + (uint32_t)(np * 16 * 80) + kb);
#pragma unroll
            for (int mt = 0; mt < 4; mt++)
#pragma unroll
                for (int nt = 0; nt < 4; nt++)
                    mma16816(acc[mt][nt], ah[mt], bh[nt >> 1][(nt & 1) * 2],
                             bh[nt >> 1][(nt & 1) * 2 + 1]);
        }
        __syncthreads();
    }

    // epilogue: bias add, fp16 round, store
#pragma unroll
    for (int mt = 0; mt < 4; mt++) {
        const int lloc = l0 + wm * 64 + mt * 16 + (lane >> 2);
#pragma unroll
        for (int nt = 0; nt < 4; nt++) {
            const int n  = nBase + wn * 32 + nt * 8 + (lane & 3) * 2;
            const int h  = n >> 6;
            const int dh = n & 63;
            const float bx = bias[n], by = bias[n + 1];
            unsigned short h00 = hfbits(__float2half_rn(acc[mt][nt][0] + bx));
            unsigned short h01 = hfbits(__float2half_rn(acc[mt][nt][1] + by));
            unsigned short h10 = hfbits(__float2half_rn(acc[mt][nt][2] + bx));
            unsigned short h11 = hfbits(__float2half_rn(acc[mt][nt][3] + by));
            if (!vtrans) {
                size_t e0 = (((size_t)b * HH + h) * Lx + lloc) * DHH + dh;
                size_t e1 = e0 + 8 * DHH;
                *(uint32_t*)(outH + e0) = (uint32_t)h00 | ((uint32_t)h01 << 16);
                *(uint32_t*)(outH + e1) = (uint32_t)h10 | ((uint32_t)h11 << 16);
            } else {
                size_t t0 = (((size_t)b * HH + h) * DHH + dh) * Lx + lloc;
                outH[t0]          = *reinterpret_cast<hf*>(&h00);
                outH[t0 + 8]      = *reinterpret_cast<hf*>(&h10);
                outH[t0 + Lx]     = *reinterpret_cast<hf*>(&h01);
                outH[t0 + Lx + 8] = *reinterpret_cast<hf*>(&h11);
            }
        }
    }
}

// ---------------------------------------------------------------------------
// HMMA fused attention (single fp16).  CTA = 128 q rows, 10 kv tiles of 64.
// Regions: QH 0 (16K) | R1 16384 (Gq -> P, 16K) | R2 32768 (Gk/K, 8K) |
//          VH 40960 (8K) | MS 49152 (256B)   total 49408 B
// ---------------------------------------------------------------------------
#define SM_QH  0u
#define SM_R1  16384u
#define SM_R2  32768u
#define SM_VH  40960u
#define SM_MS  49152u
#define ATT_SMEM 49408u

__device__ __forceinline__ uint32_t swz(uint32_t base, int row, int c16) {
    return base + (uint32_t)(row * 128) + (uint32_t)(((c16 ^ (row & 7)) << 4));
}

// single-term GEMM tile: acc[8][4] += A(16 rows/warp x 64) * B(64 x 64)
__device__ __forceinline__ void gemm1(
    float (*acc)[4], uint32_t Ab, uint32_t Bb,
    int aRow, int bRow0, int aC, int bC)
{
#pragma unroll
    for (int s = 0; s < 4; s++) {
        uint32_t ah[4];
        LDX4(ah, swz(Ab, aRow, 2 * s + aC));
#pragma unroll
        for (int ntp = 0; ntp < 4; ntp++) {
            int br = bRow0 + ntp * 16;
            uint32_t bhf[4];
            LDX4(bhf, swz(Bb, br, 2 * s + bC));
            mma16816(acc[2*ntp],   ah, bhf[0], bhf[1]);
            mma16816(acc[2*ntp+1], ah, bhf[2], bhf[3]);
        }
    }
}

__global__ __launch_bounds__(256, 2) void attn_mma(
    const hf* __restrict__ Qh,  const hf* __restrict__ Kh,
    const hf* __restrict__ Vth,
    const hf* __restrict__ GQWh,const hf* __restrict__ GQEh,
    const hf* __restrict__ GKWh,const hf* __restrict__ GKEh,
    const float* __restrict__ mask, float* __restrict__ out)
{
    extern __shared__ char smc[];
    const uint32_t smb = smem_u32(smc);

    const int tid  = threadIdx.x;
    const int wid  = tid >> 5;
    const int lane = tid & 31;

    const int qt = blockIdx.x;          // 0..4
    const int h  = blockIdx.y;
    const int b  = blockIdx.z;
    const int q0 = qt * 128;
    const bool qWord = (q0 < LW);
    const size_t bh = (size_t)(b * HH + h);

    const hf* Qhg = Qh + (bh * LL + q0) * DHH;
    const hf* Gqh = qWord ? GQWh + (bh * LW + q0) * DHH
                          : GQEh + (bh * LE + (q0 - LW)) * DHH;

    // stage Q (once): 128 rows x 8 units of 16B
#pragma unroll
    for (int u = tid; u < 1024; u += 256) {
        int row = u >> 3, c = u & 7;
        cpa16(swz(smb + SM_QH, row, c), Qhg + (size_t)row * DHH + c * 8);
    }
    CP_COMMIT();

    const int aRow  = wid * 16 + (lane & 15);
    const int aC    = lane >> 4;
    const int bRow0 = (lane & 7) + ((lane >> 4) & 1) * 8;
    const int bC    = (lane >> 3) & 1;

    float o[8][4];
#pragma unroll
    for (int t = 0; t < 8; t++)
#pragma unroll
        for (int j = 0; j < 4; j++) o[t][j] = 0.0f;
    float m0 = -1e30f, m1 = -1e30f, ls0 = 0.0f, ls1 = 0.0f;

    const int r0  = wid * 16 + (lane >> 2);
    const int prx = r0 & 7;
    const int pb  = 4 * (lane & 3);

    for (int kt = 0; kt < 10; kt++) {
        const int  k0    = kt * 64;
        const bool kWord = (k0 < LW);
        const bool cross = (kWord != qWord);

        __syncthreads();

        // ---- stage this iteration ----
        {
            if (cross) {
                const hf* gkh = qWord ? GKEh + (bh * LE + (k0 - LW)) * DHH
                                      : GKWh + (bh * LW + k0) * DHH;
#pragma unroll
                for (int u = tid; u < 1024; u += 256) {
                    int rr = u >> 3, cc = u & 7;
                    cpa16(swz(smb + SM_R1, rr, cc), Gqh + (size_t)rr * DHH + cc * 8);
                }
#pragma unroll
                for (int u = tid; u < 512; u += 256) {
                    int rr = u >> 3, cc = u & 7;
                    cpa16(swz(smb + SM_R2, rr, cc), gkh + (size_t)rr * DHH + cc * 8);
                }
            } else {
                const hf* kh = Kh + (bh * LL + k0) * DHH;
#pragma unroll
                for (int u = tid; u < 512; u += 256) {
                    int rr = u >> 3, cc = u & 7;
                    cpa16(swz(smb + SM_R2, rr, cc), kh + (size_t)rr * DHH + cc * 8);
                }
            }
            const hf* vhB = Vth + bh * DHH * LL + k0;
#pragma unroll
            for (int u = tid; u < 512; u += 256) {
                int rr = u >> 3, cc = u & 7;
                cpa16(swz(smb + SM_VH, rr, cc), vhB + (size_t)rr * LL + cc * 8);
            }
            if (tid < 16)
                cpa16(smb + SM_MS + tid * 16, mask + (size_t)b * LL + k0 + tid * 4);
            CP_COMMIT();
            CP_WAIT(0);
            __syncthreads();
        }

        float acc[8][4];
        if (cross) {
            // gate GEMM -> sigmoid transform -> becomes accumulator init
#pragma unroll
            for (int t = 0; t < 8; t++)
#pragma unroll
                for (int j = 0; j < 4; j++) acc[t][j] = 0.0f;
            gemm1(acc, smb + SM_R1, smb + SM_R2, aRow, bRow0, aC, bC);
#pragma unroll
            for (int t = 0; t < 8; t++)
#pragma unroll
                for (int j = 0; j < 4; j++)
                    acc[t][j] = -10.0f / (1.0f + __expf(-acc[t][j]));
            __syncthreads();   // done reading Gk from R2
            {
                const hf* kh = Kh + (bh * LL + k0) * DHH;
#pragma unroll
                for (int u = tid; u < 512; u += 256) {
                    int rr = u >> 3, cc = u & 7;
                    cpa16(swz(smb + SM_R2, rr, cc), kh + (size_t)rr * DHH + cc * 8);
                }
                CP_COMMIT();
                CP_WAIT(0);
                __syncthreads();
            }
        } else {
#pragma unroll
            for (int t = 0; t < 8; t++)
#pragma unroll
                for (int j = 0; j < 4; j++) acc[t][j] = -5.0f;
        }

        // S GEMM: Q * K^T accumulated onto gate
        gemm1(acc, smb + SM_QH, smb + SM_R2, aRow, bRow0, aC, bC);

        // ---- online softmax ----
        float rmax0 = -1e30f, rmax1 = -1e30f;
#pragma unroll
        for (int t = 0; t < 8; t++) {
            int colb = t * 8 + 2 * (lane & 3);
            float mk0 = *(const float*)(smc + SM_MS + (colb) * 4);
            float mk1 = *(const float*)(smc + SM_MS + (colb + 1) * 4);
            acc[t][0] = acc[t][0] * 0.125f + mk0;
            acc[t][1] = acc[t][1] * 0.125f + mk1;
            acc[t][2] = acc[t][2] * 0.125f + mk0;
            acc[t][3] = acc[t][3] * 0.125f + mk1;
            rmax0 = fmaxf(rmax0, fmaxf(acc[t][0], acc[t][1]));
            rmax1 = fmaxf(rmax1, fmaxf(acc[t][2], acc[t][3]));
        }
#pragma unroll
        for (int off = 1; off <= 2; off <<= 1) {
            rmax0 = fmaxf(rmax0, __shfl_xor_sync(0xffffffffu, rmax0, off));
            rmax1 = fmaxf(rmax1, __shfl_xor_sync(0xffffffffu, rmax1, off));
        }
        float mn0 = fmaxf(m0, rmax0), mn1 = fmaxf(m1, rmax1);
        float corr0 = __expf(m0 - mn0), corr1 = __expf(m1 - mn1);
        m0 = mn0; m1 = mn1;
        float sum0 = 0.0f, sum1 = 0.0f;
#pragma unroll
        for (int t = 0; t < 8; t++) {
            acc[t][0] = __expf(acc[t][0] - mn0);
            acc[t][1] = __expf(acc[t][1] - mn0);
            acc[t][2] = __expf(acc[t][2] - mn1);
            acc[t][3] = __expf(acc[t][3] - mn1);
            sum0 += acc[t][0] + acc[t][1];
            sum1 += acc[t][2] + acc[t][3];
        }
#pragma unroll
        for (int off = 1; off <= 2; off <<= 1) {
            sum0 += __shfl_xor_sync(0xffffffffu, sum0, off);
            sum1 += __shfl_xor_sync(0xffffffffu, sum1, off);
        }
        ls0 = ls0 * corr0 + sum0;
        ls1 = ls1 * corr1 + sum1;
#pragma unroll
        for (int t = 0; t < 8; t++) {
            o[t][0] *= corr0; o[t][1] *= corr0;
            o[t][2] *= corr1; o[t][3] *= corr1;
        }

        // ---- store P (fp16) into R1 ----
#pragma unroll
        for (int t = 0; t < 8; t++) {
            unsigned short h00 = hfbits(__float2half_rn(acc[t][0]));
            unsigned short h01 = hfbits(__float2half_rn(acc[t][1]));
            unsigned short h10 = hfbits(__float2half_rn(acc[t][2]));
            unsigned short h11 = hfbits(__float2half_rn(acc[t][3]));
            uint32_t ofs = (uint32_t)(r0 * 128 + ((t ^ prx) << 4) + pb);
            *(uint32_t*)(smc + SM_R1 + ofs) = (uint32_t)h00 | ((uint32_t)h01 << 16);
            *(uint32_t*)(smc + SM_R1 + ofs + 1024) = (uint32_t)h10 | ((uint32_t)h11 << 16);
        }
        __syncthreads();

        // ---- PV GEMM: P * V^T ----
        gemm1(o, smb + SM_R1, smb + SM_VH, aRow, bRow0, aC, bC);
    }

    // ---- epilogue ----
    float inv0 = 1.0f / ls0, inv1 = 1.0f / ls1;
    int q  = q0 + r0;
    size_t off0, off1;
    if (q < LW) {
        off0 = ((size_t)b * LW + q) * DD + h * DHH;
        off1 = ((size_t)b * LW + q + 8) * DD + h * DHH;
    } else {
        off0 = (size_t)BB * LW * DD + ((size_t)b * LE + (q - LW)) * DD + h * DHH;
        off1 = off0 + 8 * DD;
    }
#pragma unroll
    for (int t = 0; t < 8; t++) {
        int dh = t * 8 + 2 * (lane & 3);
        float2 r0v = {o[t][0] * inv0, o[t][1] * inv0};
        float2 r1v = {o[t][2] * inv1, o[t][3] * inv1};
        *(float2*)(out + off0 + dh) = r0v;
        *(float2*)(out + off1 + dh) = r1v;
    }
}

// ---------------------------------------------------------------------------
// Launch
// ---------------------------------------------------------------------------
extern "C" void kernel_launch(void* const* d_in, const int* in_sizes, int n_in,
                              void* d_out, int out_size)
{
    const float* word   = (const float*)d_in[0];
    const float* entity = (const float*)d_in[1];
    const float* mask   = (const float*)d_in[2];
    int base = (in_sizes[3] == 1) ? 4 : 3;
    const float* qw     = (const float*)d_in[base + 0];
    const float* qb     = (const float*)d_in[base + 1];
    const float* kw     = (const float*)d_in[base + 2];
    const float* kb     = (const float*)d_in[base + 3];
    const float* vw     = (const float*)d_in[base + 4];
    const float* vb     = (const float*)d_in[base + 5];
    const float* w2e_qw = (const float*)d_in[base + 6];
    const float* w2e_qb = (const float*)d_in[base + 7];
    const float* w2e_kw = (const float*)d_in[base + 8];
    const float* w2e_kb = (const float*)d_in[base + 9];
    const float* e2w_qw = (const float*)d_in[base + 10];
    const float* e2w_qb = (const float*)d_in[base + 11];
    const float* e2w_kw = (const float*)d_in[base + 12];
    const float* e2w_kb = (const float*)d_in[base + 13];

    hf *pQh,*pKh,*pVth,*pGQWh,*pGKWh,*pGQEh,*pGKEh,*pXhi,*pWhi;
    cudaGetSymbolAddress((void**)&pQh,  g_Qh);
    cudaGetSymbolAddress((void**)&pKh,  g_Kh);
    cudaGetSymbolAddress((void**)&pVth, g_Vth);
    cudaGetSymbolAddress((void**)&pGQWh,g_GQWh);
    cudaGetSymbolAddress((void**)&pGKWh,g_GKWh);
    cudaGetSymbolAddress((void**)&pGQEh,g_GQEh);
    cudaGetSymbolAddress((void**)&pGKEh,g_GKEh);
    cudaGetSymbolAddress((void**)&pXhi, g_Xhi);
    cudaGetSymbolAddress((void**)&pWhi, g_Whi);

    // ---- convert pass ----
    split_act<<<BB * LL, 256>>>(word, entity, pXhi);
    split_wt<<<dim3(32, 32, 7), dim3(32, 8)>>>(
        qw, kw, vw, w2e_qw, w2e_kw, e2w_qw, e2w_kw, pWhi);

    // ---- merged HMMA projections (one launch, 3200 CTAs) ----
    const size_t psmem = 2 * PBUF;   // 40 KB
    cudaFuncSetAttribute(proj_all,
                         cudaFuncAttributeMaxDynamicSharedMemorySize, (int)psmem);
    proj_all<<<3200, 256, psmem>>>(
        pXhi, pWhi,
        qb, kb, vb, w2e_qb, w2e_kb, e2w_qb, e2w_kb,
        pQh, pKh, pVth, pGQWh, pGKEh, pGQEh, pGKWh);

    // ---- HMMA attention ----
    cudaFuncSetAttribute(attn_mma,
                         cudaFuncAttributeMaxDynamicSharedMemorySize, (int)ATT_SMEM);
    attn_mma<<<dim3(5, HH, BB), 256, ATT_SMEM>>>(
        pQh, pKh, pVth,
        pGQWh, pGQEh, pGKWh, pGKEh,
        mask, (float*)d_out);
}